// round 6
// baseline (speedup 1.0000x reference)
#include <cuda_runtime.h>
#include <cuda_bf16.h>
#include <math.h>

#define N_NODES 100000
#define N_EDGES 1600000
#define C 64
#define MAXL 512            // per-pair-node neighbor list (Poisson(16): P(>512)~0)
#define MAXF 1026           // frontier capacity
#define MAXE 16384          // recorded level-2 edges (~550 expected)
#define BMW 3125            // bitmap words for 100k nodes
#define TPB 256
#define EPT 4
#define NB ((N_EDGES / EPT + TPB - 1) / TPB)   // 1563 blocks per scan
#define TILE 64             // layer-1 slots per SMEM tile

// ---------- device state; ZERO-state invariant maintained by K3 cleanup ----
__device__ int      g_deg[N_NODES];       // zero except during a call
__device__ int      g_slot[N_NODES];      // garbage; guarded by frontbit
__device__ unsigned g_frontbit[BMW];      // zero invariant
__device__ unsigned g_needbit[BMW];       // zero invariant
__device__ int      g_listA[MAXL], g_listB[MAXL];
__device__ int      g_cntA, g_cntB, g_nfront, g_ne, g_tick;   // zero invariant
__device__ int      g_frontier[MAXF];
__device__ int      g_esrc[MAXE], g_eslot[MAXE];
__device__ float    g_h1[MAXF * C];

// ---------- helpers ----------
__device__ __forceinline__ int sniff_is32(const void* edge) {
    const long long* e = (const long long*)edge;
    int is32 = 0;
    #pragma unroll
    for (int k = 0; k < 16; k++) {
        long long v = e[k];
        if (v < 0 || v >= N_NODES) { is32 = 1; break; }
    }
    return is32;
}

__device__ __forceinline__ int src_at(const void* edge, long long ei, int is32) {
    return is32 ? __ldg((const int*)edge + ei)
                : (int)__ldg((const long long*)edge + ei);
}

// load 4 consecutive dst values starting at edge index base (base % 4 == 0)
__device__ __forceinline__ void load_dst4(const void* edge, long long base,
                                          int is32, int d[4]) {
    if (is32) {
        const int* dp = (const int*)edge + N_EDGES;
        int4 t = *(const int4*)(dp + base);
        d[0] = t.x; d[1] = t.y; d[2] = t.z; d[3] = t.w;
    } else {
        const long long* dp = (const long long*)edge + N_EDGES;
        longlong2 a = *(const longlong2*)(dp + base);
        longlong2 b = *(const longlong2*)(dp + base + 2);
        d[0] = (int)a.x; d[1] = (int)a.y; d[2] = (int)b.x; d[3] = (int)b.y;
    }
}

__device__ __forceinline__ void fr_insert(int v) {
    if ((unsigned)v >= N_NODES) return;
    unsigned m = 1u << (v & 31);
    unsigned old = atomicOr(&g_frontbit[v >> 5], m);
    if (!(old & m)) {
        atomicOr(&g_needbit[v >> 5], m);       // frontier nodes need degrees too
        int s = atomicAdd(&g_nfront, 1);
        if (s < MAXF) { g_frontier[s] = v; g_slot[v] = s; }
    }
}

// ---------- K1: scan dst vs p0/p1 -> pair lists + frontier ----------
__global__ __launch_bounds__(TPB)
void k_scanA(const void* __restrict__ edge, const void* __restrict__ pair) {
    __shared__ int s_is32, s_p0, s_p1;
    if (threadIdx.x == 0) {
        int is32 = sniff_is32(edge);
        s_is32 = is32;
        s_p0 = is32 ? __ldg((const int*)pair)     : (int)__ldg((const long long*)pair);
        s_p1 = is32 ? __ldg((const int*)pair + 1) : (int)__ldg((const long long*)pair + 1);
    }
    __syncthreads();
    const int is32 = s_is32, p0 = s_p0, p1 = s_p1;
    if (blockIdx.x == 0 && threadIdx.x == 0) { fr_insert(p0); fr_insert(p1); }

    long long base = (blockIdx.x * (long long)TPB + threadIdx.x) * EPT;
    if (base >= N_EDGES) return;
    int d[4];
    load_dst4(edge, base, is32, d);
    #pragma unroll
    for (int k = 0; k < EPT; k++) {
        int dd = d[k];
        if (dd == p0 || dd == p1) {
            int s = src_at(edge, base + k, is32);
            if ((unsigned)s >= N_NODES) continue;
            if (dd == p0) { int j = atomicAdd(&g_cntA, 1); if (j < MAXL) g_listA[j] = s; }
            if (dd == p1) { int j = atomicAdd(&g_cntB, 1); if (j < MAXL) g_listB[j] = s; }
            fr_insert(s);
        }
    }
}

// ---------- K2: scan dst vs frontier bitmap -> record (src, slot) + needbit ----
__global__ __launch_bounds__(TPB)
void k_scanB(const void* __restrict__ edge) {
    __shared__ int s_is32;
    __shared__ unsigned s_bm[BMW];
    if (threadIdx.x == 0) s_is32 = sniff_is32(edge);
    for (int i = threadIdx.x; i < BMW; i += TPB) s_bm[i] = g_frontbit[i];
    __syncthreads();
    const int is32 = s_is32;

    long long base = (blockIdx.x * (long long)TPB + threadIdx.x) * EPT;
    if (base >= N_EDGES) return;
    int d[4];
    load_dst4(edge, base, is32, d);
    #pragma unroll
    for (int k = 0; k < EPT; k++) {
        int dd = d[k];
        if ((unsigned)dd >= N_NODES) continue;
        if ((s_bm[dd >> 5] >> (dd & 31)) & 1u) {
            int s = src_at(edge, base + k, is32);
            if ((unsigned)s >= N_NODES) continue;
            int sl = g_slot[dd];
            if ((unsigned)sl >= (unsigned)MAXF) continue;
            atomicOr(&g_needbit[s >> 5], 1u << (s & 31));
            int j = atomicAdd(&g_ne, 1);
            if (j < MAXE) { g_esrc[j] = s; g_eslot[j] = sl; }
        }
    }
}

// ---------- K3: scan dst vs needbit -> sparse degrees; last block does rest ----
__global__ __launch_bounds__(TPB)
void k_scanC(const void* __restrict__ edge, const void* __restrict__ pair,
             const float* __restrict__ x,
             const float* __restrict__ W1, const float* __restrict__ b1,
             const float* __restrict__ W2, const float* __restrict__ b2,
             const float* __restrict__ fcW, const float* __restrict__ fcb,
             float* __restrict__ out) {
    __shared__ int s_is32, s_p0, s_p1, s_last;
    __shared__ unsigned s_bm[BMW];
    __shared__ float s_agg[TILE * C];       // 16 KB
    __shared__ float s_rows[4 * C];
    __shared__ float s_fc[4 * C];           // sz[128] + sh2[128]
    if (threadIdx.x == 0) {
        int is32 = sniff_is32(edge);
        s_is32 = is32;
        s_p0 = is32 ? __ldg((const int*)pair)     : (int)__ldg((const long long*)pair);
        s_p1 = is32 ? __ldg((const int*)pair + 1) : (int)__ldg((const long long*)pair + 1);
    }
    for (int i = threadIdx.x; i < BMW; i += TPB) s_bm[i] = g_needbit[i];
    __syncthreads();
    const int is32 = s_is32;
    const int tid = threadIdx.x;

    long long base = (blockIdx.x * (long long)TPB + tid) * EPT;
    if (base < N_EDGES) {
        int d[4];
        load_dst4(edge, base, is32, d);
        #pragma unroll
        for (int k = 0; k < EPT; k++) {
            int dd = d[k];
            if ((unsigned)dd >= N_NODES) continue;
            if ((s_bm[dd >> 5] >> (dd & 31)) & 1u) atomicAdd(&g_deg[dd], 1);
        }
    }

    // ---- last-block ticket ----
    __syncthreads();
    __threadfence();
    if (tid == 0) s_last = (atomicAdd(&g_tick, 1) == (int)gridDim.x - 1) ? 1 : 0;
    __syncthreads();
    if (!s_last) return;
    __threadfence();                         // acquire all scans' atomics

    const int nf = min(__ldcg(&g_nfront), MAXF);
    const int ne = min(__ldcg(&g_ne), MAXE);
    const int c  = tid & (C - 1);
    const int el = tid >> 6;                 // 4 edge/slot lanes

    // ---- layer 1: tiles of 64 slots ----
    for (int tb = 0; tb < nf; tb += TILE) {
        int tn = min(TILE, nf - tb);
        for (int i = tid; i < TILE * C; i += TPB) s_agg[i] = 0.0f;
        __syncthreads();
        for (int j = el; j < ne; j += 4) {
            int sl = __ldcg(&g_eslot[j]);
            int lo = sl - tb;
            if ((unsigned)lo < (unsigned)tn) {
                int u = __ldcg(&g_esrc[j]);
                float w = rsqrtf((float)(__ldcg(&g_deg[u]) + 1));
                atomicAdd(&s_agg[lo * C + c], w * __ldg(&x[(size_t)u * C + c]));
            }
        }
        __syncthreads();
        for (int r = 0; r < tn; r += 4) {
            int so = r + el;
            if (so < tn) {
                int v = __ldcg(&g_frontier[tb + so]);
                float dv = rsqrtf((float)(__ldcg(&g_deg[v]) + 1));
                s_rows[el * C + c] = dv * s_agg[so * C + c]
                                   + dv * dv * __ldg(&x[(size_t)v * C + c]);
            }
            __syncthreads();
            if (so < tn) {
                const float* row = &s_rows[el * C];
                float a0 = 0.f, a1 = 0.f, a2 = 0.f, a3 = 0.f;
                #pragma unroll
                for (int k = 0; k < C; k += 4) {
                    a0 += row[k    ] * __ldg(&W1[(k    ) * C + c]);
                    a1 += row[k + 1] * __ldg(&W1[(k + 1) * C + c]);
                    a2 += row[k + 2] * __ldg(&W1[(k + 2) * C + c]);
                    a3 += row[k + 3] * __ldg(&W1[(k + 3) * C + c]);
                }
                g_h1[(tb + so) * C + c] =
                    fmaxf(__ldg(&b1[c]) + ((a0 + a1) + (a2 + a3)), 0.0f);
            }
            __syncthreads();
        }
    }

    // ---- layer 2 + fc + sigmoid ----
    float* sz  = s_fc;                       // [0..127]
    float* sh2 = s_fc + 2 * C;               // [128..255]
    if (tid < 2 * C) {
        int p = tid >> 6;
        int cc = tid & (C - 1);
        int v = (p == 0) ? s_p0 : s_p1;
        float z = 0.0f;
        if ((unsigned)v < N_NODES) {
            float dv = rsqrtf((float)(__ldcg(&g_deg[v]) + 1));
            int sv = g_slot[v];
            if ((unsigned)sv < (unsigned)MAXF) z = dv * dv * g_h1[sv * C + cc];
            int cnt = (p == 0) ? min(g_cntA, MAXL) : min(g_cntB, MAXL);
            const int* list = (p == 0) ? g_listA : g_listB;
            for (int j = 0; j < cnt; j++) {
                int u = list[j];
                int su = g_slot[u];
                if ((unsigned)su < (unsigned)MAXF)
                    z += rsqrtf((float)(__ldcg(&g_deg[u]) + 1)) * dv
                       * g_h1[su * C + cc];
            }
        }
        sz[tid] = z;
    }
    __syncthreads();
    if (tid < 2 * C) {
        int p = tid >> 6;
        int cc = tid & (C - 1);
        float acc = __ldg(&b2[cc]);
        #pragma unroll
        for (int k = 0; k < C; k++) acc += sz[p * C + k] * __ldg(&W2[k * C + cc]);
        sh2[tid] = fmaxf(acc, 0.0f) * __ldg(&fcW[tid]);
    }
    __syncthreads();
    for (int s = C; s > 0; s >>= 1) {
        if (tid < s) sh2[tid] += sh2[tid + s];
        __syncthreads();
    }
    if (tid == 0) out[0] = 1.0f / (1.0f + expf(-(sh2[0] + __ldg(&fcb[0]))));

    // ---- cleanup: restore zero-state for next replay (touched entries only) ----
    __syncthreads();
    for (int i = tid; i < nf; i += TPB) {
        int v = g_frontier[i];
        if ((unsigned)v < N_NODES) {
            g_deg[v] = 0;
            g_frontbit[v >> 5] = 0u;
            g_needbit[v >> 5] = 0u;
        }
    }
    for (int j = tid; j < ne; j += TPB) {
        int u = g_esrc[j];
        if ((unsigned)u < N_NODES) {
            g_deg[u] = 0;
            g_needbit[u >> 5] = 0u;
        }
    }
    if (tid == 0) { g_cntA = 0; g_cntB = 0; g_nfront = 0; g_ne = 0; g_tick = 0; }
}

// ---------- launch ----------
extern "C" void kernel_launch(void* const* d_in, const int* in_sizes, int n_in,
                              void* d_out, int out_size) {
    const float* x    = (const float*)d_in[0];
    const void*  edge = d_in[1];
    const void*  pair = d_in[2];
    const float* W1   = (const float*)d_in[3];
    const float* b1   = (const float*)d_in[4];
    const float* W2   = (const float*)d_in[5];
    const float* b2   = (const float*)d_in[6];
    const float* fcW  = (const float*)d_in[7];
    const float* fcb  = (const float*)d_in[8];
    float* out = (float*)d_out;

    k_scanA<<<NB, TPB>>>(edge, pair);
    k_scanB<<<NB, TPB>>>(edge);
    k_scanC<<<NB, TPB>>>(edge, pair, x, W1, b1, W2, b2, fcW, fcb, out);
}

// round 7
// speedup vs baseline: 2.2159x; 2.2159x over previous
#include <cuda_runtime.h>
#include <cuda_bf16.h>
#include <math.h>

#define N_NODES 100000
#define N_EDGES 1600000
#define C 64
#define MAXL 512            // per-pair-node neighbor list (Poisson(16): P(>512)~0)
#define MAXF 1026           // frontier capacity
#define MAXE 16384          // recorded level-2 edges (~560 expected)
#define BMW 3125            // bitmap words for 100k nodes
#define TPB 256
#define EPT 4
#define NB ((N_EDGES / EPT + TPB - 1) / TPB)   // 1563 blocks per scan

// ---------- device state; zero-invariant restored by K3 cleanup ----------
__device__ int      g_deg[N_NODES];       // zeroed in K1 each call
__device__ int      g_slot[N_NODES];      // garbage; guarded by frontbit
__device__ unsigned g_frontbit[BMW];      // zero invariant (cleanup)
__device__ int      g_listA[MAXL], g_listB[MAXL];
__device__ int      g_cntA, g_cntB, g_nfront, g_ne, g_tick;   // zero invariant
__device__ int      g_frontier[MAXF];
__device__ int      g_esrc[MAXE], g_eslot[MAXE];
__device__ float    g_h1[MAXF * C];

// ---------- helpers ----------
__device__ __forceinline__ int sniff_is32(const void* edge) {
    const long long* e = (const long long*)edge;
    int is32 = 0;
    #pragma unroll
    for (int k = 0; k < 16; k++) {
        long long v = e[k];
        if (v < 0 || v >= N_NODES) { is32 = 1; break; }
    }
    return is32;
}
__device__ __forceinline__ int src_at(const void* edge, long long ei, int is32) {
    return is32 ? __ldg((const int*)edge + ei)
                : (int)__ldg((const long long*)edge + ei);
}
__device__ __forceinline__ void load_dst4(const void* edge, long long base,
                                          int is32, int d[4]) {
    if (is32) {
        const int* dp = (const int*)edge + N_EDGES;
        int4 t = *(const int4*)(dp + base);
        d[0] = t.x; d[1] = t.y; d[2] = t.z; d[3] = t.w;
    } else {
        const long long* dp = (const long long*)edge + N_EDGES;
        longlong2 a = *(const longlong2*)(dp + base);
        longlong2 b = *(const longlong2*)(dp + base + 2);
        d[0] = (int)a.x; d[1] = (int)a.y; d[2] = (int)b.x; d[3] = (int)b.y;
    }
}
__device__ __forceinline__ void fr_insert(int v) {
    if ((unsigned)v >= N_NODES) return;
    unsigned m = 1u << (v & 31);
    unsigned old = atomicOr(&g_frontbit[v >> 5], m);
    if (!(old & m)) {
        int s = atomicAdd(&g_nfront, 1);
        if (s < MAXF) { g_frontier[s] = v; g_slot[v] = s; }
    }
}

// ---------- K1: scan dst vs p0/p1 -> pair lists + frontier; zero g_deg ----
__global__ __launch_bounds__(TPB)
void k_scanA(const void* __restrict__ edge, const void* __restrict__ pair) {
    __shared__ int s_is32, s_p0, s_p1;
    if (threadIdx.x == 0) {
        int is32 = sniff_is32(edge);
        s_is32 = is32;
        s_p0 = is32 ? __ldg((const int*)pair)     : (int)__ldg((const long long*)pair);
        s_p1 = is32 ? __ldg((const int*)pair + 1) : (int)__ldg((const long long*)pair + 1);
    }
    __syncthreads();
    const int is32 = s_is32, p0 = s_p0, p1 = s_p1;
    const int gt = blockIdx.x * TPB + threadIdx.x;
    if (gt < N_NODES) g_deg[gt] = 0;                 // NB*TPB = 400k >= N_NODES
    if (gt == 0) { fr_insert(p0); fr_insert(p1); }

    long long base = (long long)gt * EPT;
    if (base >= N_EDGES) return;
    int d[4];
    load_dst4(edge, base, is32, d);
    #pragma unroll
    for (int k = 0; k < EPT; k++) {
        int dd = d[k];
        if (dd == p0 || dd == p1) {
            int s = src_at(edge, base + k, is32);
            if ((unsigned)s >= N_NODES) continue;
            if (dd == p0) { int j = atomicAdd(&g_cntA, 1); if (j < MAXL) g_listA[j] = s; }
            if (dd == p1) { int j = atomicAdd(&g_cntB, 1); if (j < MAXL) g_listB[j] = s; }
            fr_insert(s);
        }
    }
}

// ---------- K2: scan dst -> full degree count + record frontier in-edges ----
__global__ __launch_bounds__(TPB)
void k_scanB(const void* __restrict__ edge) {
    __shared__ int s_is32;
    __shared__ unsigned s_bm[BMW];
    if (threadIdx.x == 0) s_is32 = sniff_is32(edge);
    for (int i = threadIdx.x; i < BMW; i += TPB) s_bm[i] = g_frontbit[i];
    __syncthreads();
    const int is32 = s_is32;

    long long base = (blockIdx.x * (long long)TPB + threadIdx.x) * EPT;
    if (base >= N_EDGES) return;
    int d[4];
    load_dst4(edge, base, is32, d);
    #pragma unroll
    for (int k = 0; k < EPT; k++) {
        int dd = d[k];
        if ((unsigned)dd >= N_NODES) continue;
        atomicAdd(&g_deg[dd], 1);
        if ((s_bm[dd >> 5] >> (dd & 31)) & 1u) {
            int s = src_at(edge, base + k, is32);
            if ((unsigned)s >= N_NODES) continue;
            int sl = g_slot[dd];
            if ((unsigned)sl >= (unsigned)MAXF) continue;
            int j = atomicAdd(&g_ne, 1);
            if (j < MAXE) { g_esrc[j] = s; g_eslot[j] = sl; }
        }
    }
}

// ---------- K3: parallel layer-1 per slot; last block: tail + cleanup ----
__global__ __launch_bounds__(128)
void k_final(const void* __restrict__ edge, const void* __restrict__ pair,
             const float* __restrict__ x,
             const float* __restrict__ W1, const float* __restrict__ b1,
             const float* __restrict__ W2, const float* __restrict__ b2,
             const float* __restrict__ fcW, const float* __restrict__ fcb,
             float* __restrict__ out) {
    __shared__ float sy[2 * C];
    __shared__ int s_last;
    const int tid = threadIdx.x;
    const int c = tid & (C - 1);
    const int half = tid >> 6;               // 0 or 1
    const int nf = min(g_nfront, MAXF);
    const int ne = min(g_ne, MAXE);
    const int s = blockIdx.x;

    // ---- layer 1 (one slot per block, fully parallel across grid) ----
    if (s < nf) {
        int v = g_frontier[s];
        float y = 0.0f;
        for (int j = half; j < ne; j += 2) {
            if (g_eslot[j] == s) {           // broadcast load across warp
                int u = g_esrc[j];
                y += rsqrtf((float)(g_deg[u] + 1)) * __ldg(&x[(size_t)u * C + c]);
            }
        }
        sy[tid] = y;
        __syncthreads();
        if (half == 0) {
            float dv = rsqrtf((float)(g_deg[v] + 1));
            float yy = dv * (sy[c] + sy[C + c])
                     + dv * dv * __ldg(&x[(size_t)v * C + c]);
            sy[c] = yy;
        }
        __syncthreads();
        if (half == 0) {
            float acc = __ldg(&b1[c]);
            #pragma unroll
            for (int k = 0; k < C; k++) acc += sy[k] * __ldg(&W1[k * C + c]);
            g_h1[s * C + c] = fmaxf(acc, 0.0f);
        }
    }

    // ---- last-block ticket ----
    __syncthreads();
    __threadfence();
    if (tid == 0) s_last = (atomicAdd(&g_tick, 1) == (int)gridDim.x - 1) ? 1 : 0;
    __syncthreads();
    if (!s_last) return;
    __threadfence();

    // ---- layer 2 + fc + sigmoid (tiny: 2 x ~17 list entries) ----
    __shared__ float sz[2 * C];
    __shared__ float sh2[2 * C];
    {
        int is32 = sniff_is32(edge);
        int p = half;
        int v = is32 ? __ldg((const int*)pair + p)
                     : (int)__ldg((const long long*)pair + p);
        float z = 0.0f;
        if ((unsigned)v < N_NODES) {
            float dv = rsqrtf((float)(g_deg[v] + 1));
            int sv = g_slot[v];
            if ((unsigned)sv < (unsigned)MAXF) z = dv * dv * __ldcg(&g_h1[sv * C + c]);
            int cnt = (p == 0) ? min(g_cntA, MAXL) : min(g_cntB, MAXL);
            const int* list = (p == 0) ? g_listA : g_listB;
            for (int j = 0; j < cnt; j++) {
                int u = list[j];
                int su = g_slot[u];
                if ((unsigned)su < (unsigned)MAXF)
                    z += rsqrtf((float)(g_deg[u] + 1)) * dv
                       * __ldcg(&g_h1[su * C + c]);
            }
        }
        sz[tid] = z;
    }
    __syncthreads();
    {
        float acc = __ldg(&b2[c]);
        #pragma unroll
        for (int k = 0; k < C; k++) acc += sz[half * C + k] * __ldg(&W2[k * C + c]);
        sh2[tid] = fmaxf(acc, 0.0f) * __ldg(&fcW[tid]);
    }
    __syncthreads();
    for (int st = C; st > 0; st >>= 1) {
        if (tid < st) sh2[tid] += sh2[tid + st];
        __syncthreads();
    }
    if (tid == 0) out[0] = 1.0f / (1.0f + expf(-(sh2[0] + __ldg(&fcb[0]))));

    // ---- cleanup: restore zero-state invariant for next replay ----
    __syncthreads();
    for (int i = tid; i < nf; i += 128) {
        int v = g_frontier[i];
        if ((unsigned)v < N_NODES) g_frontbit[v >> 5] = 0u;
    }
    if (tid == 0) { g_cntA = 0; g_cntB = 0; g_nfront = 0; g_ne = 0; g_tick = 0; }
}

// ---------- launch ----------
extern "C" void kernel_launch(void* const* d_in, const int* in_sizes, int n_in,
                              void* d_out, int out_size) {
    const float* x    = (const float*)d_in[0];
    const void*  edge = d_in[1];
    const void*  pair = d_in[2];
    const float* W1   = (const float*)d_in[3];
    const float* b1   = (const float*)d_in[4];
    const float* W2   = (const float*)d_in[5];
    const float* b2   = (const float*)d_in[6];
    const float* fcW  = (const float*)d_in[7];
    const float* fcb  = (const float*)d_in[8];
    float* out = (float*)d_out;

    k_scanA<<<NB, TPB>>>(edge, pair);
    k_scanB<<<NB, TPB>>>(edge);
    k_final<<<MAXF, 128>>>(edge, pair, x, W1, b1, W2, b2, fcW, fcb, out);
}

// round 8
// speedup vs baseline: 2.5206x; 1.1375x over previous
#include <cuda_runtime.h>
#include <cuda_bf16.h>
#include <math.h>

#define N_NODES 100000
#define N_EDGES 1600000
#define C 64
#define MAXL 512            // per-pair-node list (Poisson(16): P(>512)~0)
#define MAXF 1026           // frontier capacity
#define TPB 256
#define EPT 4
#define NB ((N_EDGES / EPT + TPB - 1) / TPB)   // 1563 blocks per scan

// ---------- device state (zero static-init IS the empty state) ----------
__device__ int      g_deg[N_NODES];       // zeroed by K1 each call
__device__ int      g_slot[N_NODES];      // 0 = absent, else slot+1 (cleanup restores 0)
__device__ int      g_listA[MAXL], g_listB[MAXL];
__device__ int      g_cntA, g_cntB, g_nfront, g_tick;  // cleanup restores 0
__device__ int      g_frontier[MAXF];
__device__ float    g_agg[MAXF * C];      // cleanup re-zeroes touched slots
__device__ float    g_h1[MAXF * C];

// ---------- helpers ----------
__device__ __forceinline__ int sniff_is32(const void* edge) {
    const long long* e = (const long long*)edge;
    int is32 = 0;
    #pragma unroll
    for (int k = 0; k < 16; k++) {
        long long v = e[k];
        if (v < 0 || v >= N_NODES) { is32 = 1; break; }
    }
    return is32;
}
__device__ __forceinline__ int src_at(const void* edge, long long ei, int is32) {
    return is32 ? __ldg((const int*)edge + ei)
                : (int)__ldg((const long long*)edge + ei);
}
__device__ __forceinline__ void load_dst4(const void* edge, long long base,
                                          int is32, int d[4]) {
    if (is32) {
        const int* dp = (const int*)edge + N_EDGES;
        int4 t = *(const int4*)(dp + base);
        d[0] = t.x; d[1] = t.y; d[2] = t.z; d[3] = t.w;
    } else {
        const long long* dp = (const long long*)edge + N_EDGES;
        longlong2 a = *(const longlong2*)(dp + base);
        longlong2 b = *(const longlong2*)(dp + base + 2);
        d[0] = (int)a.x; d[1] = (int)a.y; d[2] = (int)b.x; d[3] = (int)b.y;
    }
}
// dedup insert; g_slot: 0 = absent, -1 = claimed, s+1 = assigned
__device__ __forceinline__ void fr_insert(int v) {
    if ((unsigned)v >= N_NODES) return;
    if (atomicCAS(&g_slot[v], 0, -1) == 0) {
        int s = atomicAdd(&g_nfront, 1);
        if (s < MAXF) g_frontier[s] = v;
        g_slot[v] = s + 1;
    }
}

// ---------- K1: zero deg; scan dst vs p0/p1 -> pair lists + frontier ----
__global__ __launch_bounds__(TPB)
void k_scan1(const void* __restrict__ edge, const void* __restrict__ pair) {
    __shared__ int s_is32, s_p0, s_p1;
    if (threadIdx.x == 0) {
        int is32 = sniff_is32(edge);
        s_is32 = is32;
        s_p0 = is32 ? __ldg((const int*)pair)     : (int)__ldg((const long long*)pair);
        s_p1 = is32 ? __ldg((const int*)pair + 1) : (int)__ldg((const long long*)pair + 1);
    }
    __syncthreads();
    const int is32 = s_is32, p0 = s_p0, p1 = s_p1;
    const int gt = blockIdx.x * TPB + threadIdx.x;
    if (gt < N_NODES) g_deg[gt] = 0;               // NB*TPB = 400k >= N_NODES
    if (gt == 0) { fr_insert(p0); fr_insert(p1); }

    long long base = (long long)gt * EPT;
    if (base >= N_EDGES) return;
    int d[4];
    load_dst4(edge, base, is32, d);
    #pragma unroll
    for (int k = 0; k < EPT; k++) {
        int dd = d[k];
        if (dd == p0 || dd == p1) {
            int s = src_at(edge, base + k, is32);
            if ((unsigned)s >= N_NODES) continue;
            if (dd == p0) { int j = atomicAdd(&g_cntA, 1); if (j < MAXL) g_listA[j] = s; }
            if (dd == p1) { int j = atomicAdd(&g_cntB, 1); if (j < MAXL) g_listB[j] = s; }
            fr_insert(s);
        }
    }
}

// ---------- K2: scan dst -> degree counts + fused layer-1 aggregation ----
// edge (s -> d in frontier): agg[slot(d)] += rsqrt(deg[s]+1)*x[s]  (deg via 2nd pass
// is wrong -- so aggregate WITHOUT weight? No: R3 proved deg is complete here only
// because its scan2 ran after scan1 finished deg. Here deg is counted in THIS pass,
// so weight must come later: aggregate raw x, and apply per-src weight... that is
// impossible after summation. Therefore keep R3 semantics: deg counted in K1? No --
// R3 counted deg in scan1. So count deg in K1 here too? K1 already streams edges;
// add the atomicAdd there and K2 only aggregates. )
__global__ __launch_bounds__(TPB)
void k_scan2(const void* __restrict__ edge, const float* __restrict__ x) {
    __shared__ int s_is32;
    if (threadIdx.x == 0) s_is32 = sniff_is32(edge);
    __syncthreads();
    const int is32 = s_is32;

    long long base = (blockIdx.x * (long long)TPB + threadIdx.x) * EPT;
    if (base >= N_EDGES) return;
    int d[4];
    load_dst4(edge, base, is32, d);
    #pragma unroll
    for (int k = 0; k < EPT; k++) {
        int dd = d[k];
        if ((unsigned)dd >= N_NODES) continue;
        int sl = g_slot[dd];
        if (sl > 0 && sl <= MAXF) {
            int s = src_at(edge, base + k, is32);
            if ((unsigned)s >= N_NODES) continue;
            float w = rsqrtf((float)(__ldcg(&g_deg[s]) + 1));
            const float4* xr = (const float4*)(x + (size_t)s * C);
            float* ag = g_agg + (size_t)(sl - 1) * C;
            #pragma unroll
            for (int c4 = 0; c4 < C / 4; c4++) {
                float4 v = __ldg(xr + c4);
                atomicAdd(ag + 4 * c4 + 0, w * v.x);
                atomicAdd(ag + 4 * c4 + 1, w * v.y);
                atomicAdd(ag + 4 * c4 + 2, w * v.z);
                atomicAdd(ag + 4 * c4 + 3, w * v.w);
            }
        }
    }
}

// ---------- K1b: degree pass (must complete before K2 reads deg) ----------
__global__ __launch_bounds__(TPB)
void k_deg(const void* __restrict__ edge) {
    __shared__ int s_is32;
    if (threadIdx.x == 0) s_is32 = sniff_is32(edge);
    __syncthreads();
    const int is32 = s_is32;
    long long base = (blockIdx.x * (long long)TPB + threadIdx.x) * EPT;
    if (base >= N_EDGES) return;
    int d[4];
    load_dst4(edge, base, is32, d);
    #pragma unroll
    for (int k = 0; k < EPT; k++) {
        int dd = d[k];
        if ((unsigned)dd < N_NODES) atomicAdd(&g_deg[dd], 1);
    }
}

// ---------- K3: layer-1 matvec per slot; last block: tail + cleanup ----
__global__ __launch_bounds__(C)
void k_layer1(const void* __restrict__ edge, const void* __restrict__ pair,
              const float* __restrict__ x,
              const float* __restrict__ W1, const float* __restrict__ b1,
              const float* __restrict__ W2, const float* __restrict__ b2,
              const float* __restrict__ fcW, const float* __restrict__ fcb,
              float* __restrict__ out) {
    __shared__ float sy[C];
    __shared__ int s_last;
    const int tid = threadIdx.x;               // 64 threads
    const int nf = min(g_nfront, MAXF);
    const int s = blockIdx.x;

    if (s < nf) {
        int v = g_frontier[s];
        float dv = rsqrtf((float)(g_deg[v] + 1));
        sy[tid] = dv * g_agg[s * C + tid]
                + dv * dv * __ldg(&x[(size_t)v * C + tid]);
        __syncthreads();
        float acc = __ldg(&b1[tid]);
        #pragma unroll
        for (int k = 0; k < C; k++) acc += sy[k] * __ldg(&W1[k * C + tid]);
        g_h1[s * C + tid] = fmaxf(acc, 0.0f);
    }

    // ---- last-block ticket ----
    __syncthreads();
    __threadfence();
    if (tid == 0) s_last = (atomicAdd(&g_tick, 1) == (int)gridDim.x - 1) ? 1 : 0;
    __syncthreads();
    if (!s_last) return;
    __threadfence();

    // ---- layer 2 + fc + sigmoid (64 threads; loop p = 0,1) ----
    __shared__ float sz[2 * C];
    __shared__ float sh2[2 * C];
    int is32 = sniff_is32(edge);
    for (int p = 0; p < 2; p++) {
        int v = is32 ? __ldg((const int*)pair + p)
                     : (int)__ldg((const long long*)pair + p);
        float z = 0.0f;
        if ((unsigned)v < N_NODES) {
            float dv = rsqrtf((float)(g_deg[v] + 1));
            int sv = g_slot[v];
            if (sv > 0 && sv <= MAXF) z = dv * dv * __ldcg(&g_h1[(sv - 1) * C + tid]);
            int cnt = (p == 0) ? min(g_cntA, MAXL) : min(g_cntB, MAXL);
            const int* list = (p == 0) ? g_listA : g_listB;
            for (int j = 0; j < cnt; j++) {
                int u = list[j];
                int su = g_slot[u];
                if (su > 0 && su <= MAXF)
                    z += rsqrtf((float)(g_deg[u] + 1)) * dv
                       * __ldcg(&g_h1[(su - 1) * C + tid]);
            }
        }
        sz[p * C + tid] = z;
    }
    __syncthreads();
    for (int p = 0; p < 2; p++) {
        float acc = __ldg(&b2[tid]);
        #pragma unroll
        for (int k = 0; k < C; k++) acc += sz[p * C + k] * __ldg(&W2[k * C + tid]);
        sh2[p * C + tid] = fmaxf(acc, 0.0f) * __ldg(&fcW[p * C + tid]);
    }
    __syncthreads();
    for (int st = C; st > 0; st >>= 1) {
        if (tid < st) sh2[tid] += sh2[tid + st];
        __syncthreads();
    }
    if (tid == 0) out[0] = 1.0f / (1.0f + expf(-(sh2[0] + __ldg(&fcb[0]))));

    // ---- cleanup: restore zero-state invariant for next replay ----
    __syncthreads();
    for (int i = 0; i < nf; i++) {
        int v = g_frontier[i];
        if (tid == 0 && (unsigned)v < N_NODES) g_slot[v] = 0;
        g_agg[i * C + tid] = 0.0f;
    }
    if (tid == 0) { g_cntA = 0; g_cntB = 0; g_nfront = 0; g_tick = 0; }
}

// ---------- launch ----------
extern "C" void kernel_launch(void* const* d_in, const int* in_sizes, int n_in,
                              void* d_out, int out_size) {
    const float* x    = (const float*)d_in[0];
    const void*  edge = d_in[1];
    const void*  pair = d_in[2];
    const float* W1   = (const float*)d_in[3];
    const float* b1   = (const float*)d_in[4];
    const float* W2   = (const float*)d_in[5];
    const float* b2   = (const float*)d_in[6];
    const float* fcW  = (const float*)d_in[7];
    const float* fcb  = (const float*)d_in[8];
    float* out = (float*)d_out;

    k_scan1<<<NB, TPB>>>(edge, pair);
    k_deg<<<NB, TPB>>>(edge);
    k_scan2<<<NB, TPB>>>(edge, x);
    k_layer1<<<MAXF, C>>>(edge, pair, x, W1, b1, W2, b2, fcW, fcb, out);
}

// round 9
// speedup vs baseline: 3.7435x; 1.4852x over previous
#include <cuda_runtime.h>
#include <cuda_bf16.h>
#include <math.h>

#define N_NODES 100000
#define N_EDGES 1600000
#define C 64
#define MAXL 512            // per-pair-node list (Poisson(16): P(>512)~0)
#define MAXF 1026           // frontier capacity
#define MAXE 8192           // recorded level-2 edges (~560 expected)
#define MAXM 256            // matches per slot (in-degree cap, Poisson(16))
#define BMW 3125            // bitmap words for 100k nodes
#define TPB 256
#define EPT 4
#define NB ((N_EDGES / EPT + TPB - 1) / TPB)   // 1563 blocks per scan

// ---------- device state; zero-invariant restored by K3 tail cleanup ----------
__device__ int      g_deg[N_NODES];       // zeroed by K1 each call
__device__ unsigned g_frontbit[BMW];      // zero invariant
__device__ int      g_slot[N_NODES];      // garbage; valid where frontbit set this call
__device__ int      g_listA[MAXL], g_listB[MAXL];
__device__ int      g_cntA, g_cntB, g_nfront, g_ne, g_tick;  // zero invariant
__device__ int      g_frontier[MAXF];
__device__ int      g_esrc[MAXE], g_eslot[MAXE];
__device__ float    g_h1[MAXF * C];

// ---------- helpers ----------
__device__ __forceinline__ int sniff_is32(const void* edge) {
    const long long* e = (const long long*)edge;
    int is32 = 0;
    #pragma unroll
    for (int k = 0; k < 16; k++) {
        long long v = e[k];
        if (v < 0 || v >= N_NODES) { is32 = 1; break; }
    }
    return is32;
}
__device__ __forceinline__ int src_at(const void* edge, long long ei, int is32) {
    return is32 ? __ldg((const int*)edge + ei)
                : (int)__ldg((const long long*)edge + ei);
}
__device__ __forceinline__ void load_dst4(const void* edge, long long base,
                                          int is32, int d[4]) {
    if (is32) {
        const int* dp = (const int*)edge + N_EDGES;
        int4 t = *(const int4*)(dp + base);
        d[0] = t.x; d[1] = t.y; d[2] = t.z; d[3] = t.w;
    } else {
        const long long* dp = (const long long*)edge + N_EDGES;
        longlong2 a = *(const longlong2*)(dp + base);
        longlong2 b = *(const longlong2*)(dp + base + 2);
        d[0] = (int)a.x; d[1] = (int)a.y; d[2] = (int)b.x; d[3] = (int)b.y;
    }
}
// dedup via bitmap; slot written only by the winning thread (read next launch)
__device__ __forceinline__ void fr_insert(int v) {
    if ((unsigned)v >= N_NODES) return;
    unsigned m = 1u << (v & 31);
    unsigned old = atomicOr(&g_frontbit[v >> 5], m);
    if (!(old & m)) {
        int s = atomicAdd(&g_nfront, 1);
        if (s < MAXF) { g_frontier[s] = v; g_slot[v] = s; }
    }
}

// ---------- K1: zero deg; scan dst vs p0/p1 -> pair lists + frontier ----
__global__ __launch_bounds__(TPB)
void k_scan1(const void* __restrict__ edge, const void* __restrict__ pair) {
    __shared__ int s_is32, s_p0, s_p1;
    if (threadIdx.x == 0) {
        int is32 = sniff_is32(edge);
        s_is32 = is32;
        s_p0 = is32 ? __ldg((const int*)pair)     : (int)__ldg((const long long*)pair);
        s_p1 = is32 ? __ldg((const int*)pair + 1) : (int)__ldg((const long long*)pair + 1);
    }
    __syncthreads();
    const int is32 = s_is32, p0 = s_p0, p1 = s_p1;
    const int gt = blockIdx.x * TPB + threadIdx.x;
    if (gt < N_NODES) g_deg[gt] = 0;               // NB*TPB = 400k >= N_NODES
    if (gt == 0) { fr_insert(p0); fr_insert(p1); }

    long long base = (long long)gt * EPT;
    if (base >= N_EDGES) return;
    int d[4];
    load_dst4(edge, base, is32, d);
    #pragma unroll
    for (int k = 0; k < EPT; k++) {
        int dd = d[k];
        if (dd == p0 || dd == p1) {
            int s = src_at(edge, base + k, is32);
            if ((unsigned)s >= N_NODES) continue;
            if (dd == p0) { int j = atomicAdd(&g_cntA, 1); if (j < MAXL) g_listA[j] = s; }
            if (dd == p1) { int j = atomicAdd(&g_cntB, 1); if (j < MAXL) g_listB[j] = s; }
            fr_insert(s);
        }
    }
}

// ---------- K2: scan dst -> full degrees + record frontier in-edges ----
__global__ __launch_bounds__(TPB)
void k_scan2(const void* __restrict__ edge) {
    __shared__ int s_is32;
    __shared__ unsigned s_bm[BMW];
    if (threadIdx.x == 0) s_is32 = sniff_is32(edge);
    for (int i = threadIdx.x; i < BMW; i += TPB) s_bm[i] = g_frontbit[i];
    __syncthreads();
    const int is32 = s_is32;

    long long base = (blockIdx.x * (long long)TPB + threadIdx.x) * EPT;
    if (base >= N_EDGES) return;
    int d[4];
    load_dst4(edge, base, is32, d);
    #pragma unroll
    for (int k = 0; k < EPT; k++) {
        int dd = d[k];
        if ((unsigned)dd >= N_NODES) continue;
        atomicAdd(&g_deg[dd], 1);
        if ((s_bm[dd >> 5] >> (dd & 31)) & 1u) {
            int s = src_at(edge, base + k, is32);
            if ((unsigned)s >= N_NODES) continue;
            int sl = g_slot[dd];
            if ((unsigned)sl >= (unsigned)MAXF) continue;
            int j = atomicAdd(&g_ne, 1);
            if (j < MAXE) { g_esrc[j] = s; g_eslot[j] = sl; }
        }
    }
}

// ---------- K3: layer-1 per slot (parallel); last block: parallel tail ----
__global__ __launch_bounds__(128)
void k_layer1(const void* __restrict__ edge, const void* __restrict__ pair,
              const float* __restrict__ x,
              const float* __restrict__ W1, const float* __restrict__ b1,
              const float* __restrict__ W2, const float* __restrict__ b2,
              const float* __restrict__ fcW, const float* __restrict__ fcb,
              float* __restrict__ out) {
    __shared__ int   s_mu[MAXM];
    __shared__ float s_w[MAXM];
    __shared__ float s_red[2 * C];
    __shared__ int   s_nm, s_last;
    const int tid = threadIdx.x;
    const int c   = tid & (C - 1);
    const int grp = tid >> 6;                 // 0 or 1
    const int nf  = min(g_nfront, MAXF);
    const int ne  = min(g_ne, MAXE);
    const int s   = blockIdx.x;

    if (s < nf) {
        if (tid == 0) s_nm = 0;
        __syncthreads();
        // A: cooperative match collection (wide, pipelined broadcast loads)
        for (int j = tid; j < ne; j += 128) {
            if (g_eslot[j] == s) {
                int m = atomicAdd(&s_nm, 1);
                if (m < MAXM) s_mu[m] = g_esrc[j];
            }
        }
        __syncthreads();
        int nm = min(s_nm, MAXM);
        // B: parallel weight prefetch
        if (tid < nm) s_w[tid] = rsqrtf((float)(g_deg[s_mu[tid]] + 1));
        __syncthreads();
        // C: channel-parallel gather, 2 groups, pipelined __ldg
        float y = 0.0f;
        for (int m = grp; m < nm; m += 2)
            y += s_w[m] * __ldg(&x[(size_t)s_mu[m] * C + c]);
        s_red[tid] = y;
        __syncthreads();
        int v = g_frontier[s];
        float dv = rsqrtf((float)(g_deg[v] + 1));
        if (grp == 0)
            s_red[c] = dv * (s_red[c] + s_red[C + c])
                     + dv * dv * __ldg(&x[(size_t)v * C + c]);
        __syncthreads();
        // D: 64x64 matvec
        if (grp == 0) {
            float acc = __ldg(&b1[c]);
            #pragma unroll
            for (int k = 0; k < C; k++) acc += s_red[k] * __ldg(&W1[k * C + c]);
            g_h1[s * C + c] = fmaxf(acc, 0.0f);
        }
    }

    // ---- last-block ticket ----
    __syncthreads();
    __threadfence();
    if (tid == 0) s_last = (atomicAdd(&g_tick, 1) == (int)gridDim.x - 1) ? 1 : 0;
    __syncthreads();
    if (!s_last) return;
    __threadfence();

    // ================= tail (fully lane-parallel) =================
    __shared__ int   t_su[2 * MAXL];
    __shared__ float t_w[2 * MAXL];
    __shared__ int   t_cnt[2], t_sv[2];
    __shared__ float t_dv[2];
    {
        int is32 = sniff_is32(edge);
        if (tid < 2) {
            int v = is32 ? __ldg((const int*)pair + tid)
                         : (int)__ldg((const long long*)pair + tid);
            t_sv[tid] = -1;
            t_dv[tid] = 0.0f;
            t_cnt[tid] = 0;
            if ((unsigned)v < N_NODES) {
                t_dv[tid] = rsqrtf((float)(g_deg[v] + 1));
                int sv = g_slot[v];
                t_sv[tid] = ((unsigned)sv < (unsigned)MAXF) ? sv : -1;
                t_cnt[tid] = (tid == 0) ? min(g_cntA, MAXL) : min(g_cntB, MAXL);
            }
        }
        __syncthreads();
        // wide prefetch of list slots + weights (two dependent rounds, 128 lanes)
        for (int p = 0; p < 2; p++) {
            int cnt = t_cnt[p];
            const int* list = (p == 0) ? g_listA : g_listB;
            for (int j = tid; j < cnt; j += 128) {
                int u = list[j];
                int su = ((unsigned)u < N_NODES) ? g_slot[u] : -1;
                t_su[p * MAXL + j] = ((unsigned)su < (unsigned)MAXF) ? su : -1;
                t_w[p * MAXL + j] = ((unsigned)u < N_NODES)
                                  ? rsqrtf((float)(g_deg[u] + 1)) : 0.0f;
            }
        }
    }
    __syncthreads();
    // z[p][c]: independent pipelined __ldcg h1 reads (addresses all in shared)
    float* sz  = (float*)s_mu;                // reuse shared (256 floats)
    {
        int p = grp;
        float dv = t_dv[p];
        float z = 0.0f;
        int sv = t_sv[p];
        if (sv >= 0) z = dv * dv * __ldcg(&g_h1[sv * C + c]);
        int cnt = t_cnt[p];
        for (int j = 0; j < cnt; j++) {
            int su = t_su[p * MAXL + j];
            if (su >= 0) z += t_w[p * MAXL + j] * dv * __ldcg(&g_h1[su * C + c]);
        }
        sz[tid] = z;
    }
    __syncthreads();
    {
        float acc = __ldg(&b2[c]);
        #pragma unroll
        for (int k = 0; k < C; k++) acc += sz[grp * C + k] * __ldg(&W2[k * C + c]);
        s_red[tid] = fmaxf(acc, 0.0f) * __ldg(&fcW[tid]);
    }
    __syncthreads();
    for (int st = C; st > 0; st >>= 1) {
        if (tid < st) s_red[tid] += s_red[tid + st];
        __syncthreads();
    }
    if (tid == 0) out[0] = 1.0f / (1.0f + expf(-(s_red[0] + __ldg(&fcb[0]))));

    // ---- cleanup (parallel): restore zero-state for next replay ----
    __syncthreads();
    for (int i = tid; i < nf; i += 128) {
        int v = g_frontier[i];
        if ((unsigned)v < N_NODES) g_frontbit[v >> 5] = 0u;
    }
    if (tid == 0) { g_cntA = 0; g_cntB = 0; g_nfront = 0; g_ne = 0; g_tick = 0; }
}

// ---------- launch ----------
extern "C" void kernel_launch(void* const* d_in, const int* in_sizes, int n_in,
                              void* d_out, int out_size) {
    const float* x    = (const float*)d_in[0];
    const void*  edge = d_in[1];
    const void*  pair = d_in[2];
    const float* W1   = (const float*)d_in[3];
    const float* b1   = (const float*)d_in[4];
    const float* W2   = (const float*)d_in[5];
    const float* b2   = (const float*)d_in[6];
    const float* fcW  = (const float*)d_in[7];
    const float* fcb  = (const float*)d_in[8];
    float* out = (float*)d_out;

    k_scan1<<<NB, TPB>>>(edge, pair);
    k_scan2<<<NB, TPB>>>(edge);
    k_layer1<<<MAXF, 128>>>(edge, pair, x, W1, b1, W2, b2, fcW, fcb, out);
}

// round 10
// speedup vs baseline: 3.9358x; 1.0514x over previous
#include <cuda_runtime.h>
#include <cuda_bf16.h>
#include <math.h>

#define N_NODES 100000
#define N_EDGES 1600000
#define C 64
#define MAXL 512            // per-pair-node list (Poisson(16): P(>512)~0)
#define MAXF 1026           // frontier capacity
#define MAXE 8192           // recorded level-2 edges (~560 expected)
#define MAXM 256            // matches per slot (in-degree cap)
#define BMW 3125            // frontbit words (dedup only, touched words cleaned)
#define BLW 256             // bloom words (8192 bits, 1 KB)
#define TPB 256
#define EPT 4
#define NB ((N_EDGES / EPT + TPB - 1) / TPB)   // 1563 blocks per scan
#define K3B 256             // K3 grid

__device__ __forceinline__ unsigned bloom_bit(int v) {
    return ((unsigned)v * 2654435761u) >> 19;      // 13-bit index [0, 8192)
}

// ---------- device state; zero-invariant restored by K3 tail cleanup ----------
__device__ int      g_deg[N_NODES];       // zeroed by K1 each call
__device__ unsigned g_frontbit[BMW];      // dedup; zero invariant
__device__ unsigned g_bloom[BLW];         // membership filter; zero invariant
__device__ int      g_slot[N_NODES];      // dirty OK; validated via g_frontier
__device__ int      g_listA[MAXL], g_listB[MAXL];
__device__ int      g_cntA, g_cntB, g_nfront, g_ne, g_tick;  // zero invariant
__device__ int      g_frontier[MAXF];
__device__ int      g_esrc[MAXE], g_eslot[MAXE];
__device__ float    g_h1[MAXF * C];

// ---------- helpers ----------
__device__ __forceinline__ int sniff_is32(const void* edge) {
    const long long* e = (const long long*)edge;
    int is32 = 0;
    #pragma unroll
    for (int k = 0; k < 16; k++) {
        long long v = e[k];
        if (v < 0 || v >= N_NODES) { is32 = 1; break; }
    }
    return is32;
}
__device__ __forceinline__ int src_at(const void* edge, long long ei, int is32) {
    return is32 ? __ldg((const int*)edge + ei)
                : (int)__ldg((const long long*)edge + ei);
}
__device__ __forceinline__ void load_dst4(const void* edge, long long base,
                                          int is32, int d[4]) {
    if (is32) {
        const int* dp = (const int*)edge + N_EDGES;
        int4 t = *(const int4*)(dp + base);
        d[0] = t.x; d[1] = t.y; d[2] = t.z; d[3] = t.w;
    } else {
        const long long* dp = (const long long*)edge + N_EDGES;
        longlong2 a = *(const longlong2*)(dp + base);
        longlong2 b = *(const longlong2*)(dp + base + 2);
        d[0] = (int)a.x; d[1] = (int)a.y; d[2] = (int)b.x; d[3] = (int)b.y;
    }
}
__device__ __forceinline__ void fr_insert(int v) {
    if ((unsigned)v >= N_NODES) return;
    unsigned m = 1u << (v & 31);
    unsigned old = atomicOr(&g_frontbit[v >> 5], m);
    if (!(old & m)) {
        unsigned b = bloom_bit(v);
        atomicOr(&g_bloom[b >> 5], 1u << (b & 31));
        int s = atomicAdd(&g_nfront, 1);
        if (s < MAXF) { g_frontier[s] = v; g_slot[v] = s; }
    }
}

// ---------- K1: zero deg; scan dst vs p0/p1 -> pair lists + frontier ----
__global__ __launch_bounds__(TPB)
void k_scan1(const void* __restrict__ edge, const void* __restrict__ pair) {
    __shared__ int s_is32, s_p0, s_p1;
    if (threadIdx.x == 0) {
        int is32 = sniff_is32(edge);
        s_is32 = is32;
        s_p0 = is32 ? __ldg((const int*)pair)     : (int)__ldg((const long long*)pair);
        s_p1 = is32 ? __ldg((const int*)pair + 1) : (int)__ldg((const long long*)pair + 1);
    }
    __syncthreads();
    const int is32 = s_is32, p0 = s_p0, p1 = s_p1;
    const int gt = blockIdx.x * TPB + threadIdx.x;
    if (gt < N_NODES) g_deg[gt] = 0;               // NB*TPB = 400k >= N_NODES
    if (gt == 0) { fr_insert(p0); fr_insert(p1); }

    long long base = (long long)gt * EPT;
    if (base >= N_EDGES) return;
    int d[4];
    load_dst4(edge, base, is32, d);
    #pragma unroll
    for (int k = 0; k < EPT; k++) {
        int dd = d[k];
        if (dd == p0 || dd == p1) {
            int s = src_at(edge, base + k, is32);
            if ((unsigned)s >= N_NODES) continue;
            if (dd == p0) { int j = atomicAdd(&g_cntA, 1); if (j < MAXL) g_listA[j] = s; }
            if (dd == p1) { int j = atomicAdd(&g_cntB, 1); if (j < MAXL) g_listB[j] = s; }
            fr_insert(s);
        }
    }
}

// ---------- K2: scan dst -> full degrees + bloom-probed edge recording ----
__global__ __launch_bounds__(TPB)
void k_scan2(const void* __restrict__ edge) {
    __shared__ int s_is32;
    __shared__ unsigned s_bl[BLW];                 // 1 KB bloom in SMEM
    if (threadIdx.x == 0) s_is32 = sniff_is32(edge);
    if (threadIdx.x < BLW) s_bl[threadIdx.x] = g_bloom[threadIdx.x];
    __syncthreads();
    const int is32 = s_is32;

    long long base = (blockIdx.x * (long long)TPB + threadIdx.x) * EPT;
    if (base >= N_EDGES) return;
    int d[4];
    load_dst4(edge, base, is32, d);
    #pragma unroll
    for (int k = 0; k < EPT; k++) {
        int dd = d[k];
        if ((unsigned)dd >= N_NODES) continue;
        atomicAdd(&g_deg[dd], 1);
        unsigned b = bloom_bit(dd);
        if ((s_bl[b >> 5] >> (b & 31)) & 1u) {     // ~0.4% of edges pass
            int sl = g_slot[dd];
            if ((unsigned)sl < (unsigned)MAXF && g_frontier[sl] == dd) {  // exact
                int s = src_at(edge, base + k, is32);
                if ((unsigned)s >= N_NODES) continue;
                int j = atomicAdd(&g_ne, 1);
                if (j < MAXE) { g_esrc[j] = s; g_eslot[j] = sl; }
            }
        }
    }
}

// ---------- K3: layer-1 (slot loop); last block: parallel tail + cleanup ----
__global__ __launch_bounds__(128)
void k_layer1(const void* __restrict__ edge, const void* __restrict__ pair,
              const float* __restrict__ x,
              const float* __restrict__ W1, const float* __restrict__ b1,
              const float* __restrict__ W2, const float* __restrict__ b2,
              const float* __restrict__ fcW, const float* __restrict__ fcb,
              float* __restrict__ out) {
    __shared__ int   s_mu[MAXM];
    __shared__ float s_w[MAXM];
    __shared__ float s_red[2 * C];
    __shared__ int   s_nm, s_last;
    const int tid = threadIdx.x;
    const int c   = tid & (C - 1);
    const int grp = tid >> 6;                 // 0 or 1
    const int nf  = min(g_nfront, MAXF);
    const int ne  = min(g_ne, MAXE);

    for (int s = blockIdx.x; s < nf; s += K3B) {
        if (tid == 0) s_nm = 0;
        __syncthreads();
        for (int j = tid; j < ne; j += 128) {       // wide match collection
            if (g_eslot[j] == s) {
                int m = atomicAdd(&s_nm, 1);
                if (m < MAXM) s_mu[m] = g_esrc[j];
            }
        }
        __syncthreads();
        int nm = min(s_nm, MAXM);
        if (tid < nm) s_w[tid] = rsqrtf((float)(g_deg[s_mu[tid]] + 1));
        __syncthreads();
        float y = 0.0f;
        for (int m = grp; m < nm; m += 2)           // pipelined x gather
            y += s_w[m] * __ldg(&x[(size_t)s_mu[m] * C + c]);
        s_red[tid] = y;
        __syncthreads();
        int v = g_frontier[s];
        float dv = rsqrtf((float)(g_deg[v] + 1));
        if (grp == 0)
            s_red[c] = dv * (s_red[c] + s_red[C + c])
                     + dv * dv * __ldg(&x[(size_t)v * C + c]);
        __syncthreads();
        if (grp == 0) {
            float acc = __ldg(&b1[c]);
            #pragma unroll
            for (int k = 0; k < C; k++) acc += s_red[k] * __ldg(&W1[k * C + c]);
            g_h1[s * C + c] = fmaxf(acc, 0.0f);
        }
        __syncthreads();
    }

    // ---- last-block ticket ----
    __threadfence();
    if (tid == 0) s_last = (atomicAdd(&g_tick, 1) == K3B - 1) ? 1 : 0;
    __syncthreads();
    if (!s_last) return;
    __threadfence();

    // ================= tail (lane-parallel) =================
    __shared__ int   t_su[2 * MAXL];
    __shared__ float t_w[2 * MAXL];
    __shared__ int   t_cnt[2], t_sv[2];
    __shared__ float t_dv[2];
    {
        int is32 = sniff_is32(edge);
        if (tid < 2) {
            int v = is32 ? __ldg((const int*)pair + tid)
                         : (int)__ldg((const long long*)pair + tid);
            t_sv[tid] = -1; t_dv[tid] = 0.0f; t_cnt[tid] = 0;
            if ((unsigned)v < N_NODES) {
                t_dv[tid] = rsqrtf((float)(g_deg[v] + 1));
                int sv = g_slot[v];
                t_sv[tid] = ((unsigned)sv < (unsigned)MAXF && g_frontier[sv] == v)
                          ? sv : -1;
                t_cnt[tid] = (tid == 0) ? min(g_cntA, MAXL) : min(g_cntB, MAXL);
            }
        }
        __syncthreads();
        for (int p = 0; p < 2; p++) {               // wide slot/weight prefetch
            int cnt = t_cnt[p];
            const int* list = (p == 0) ? g_listA : g_listB;
            for (int j = tid; j < cnt; j += 128) {
                int u = list[j];
                int su = ((unsigned)u < N_NODES) ? g_slot[u] : -1;
                t_su[p * MAXL + j] =
                    ((unsigned)su < (unsigned)MAXF && g_frontier[su] == u) ? su : -1;
                t_w[p * MAXL + j] = ((unsigned)u < N_NODES)
                                  ? rsqrtf((float)(g_deg[u] + 1)) : 0.0f;
            }
        }
    }
    __syncthreads();
    float* sz = (float*)s_mu;                       // reuse shared (256 floats)
    {
        int p = grp;
        float dv = t_dv[p];
        float z = 0.0f;
        int sv = t_sv[p];
        if (sv >= 0) z = dv * dv * __ldcg(&g_h1[sv * C + c]);
        int cnt = t_cnt[p];
        for (int j = 0; j < cnt; j++) {             // independent pipelined loads
            int su = t_su[p * MAXL + j];
            if (su >= 0) z += t_w[p * MAXL + j] * dv * __ldcg(&g_h1[su * C + c]);
        }
        sz[tid] = z;
    }
    __syncthreads();
    {
        float acc = __ldg(&b2[c]);
        #pragma unroll
        for (int k = 0; k < C; k++) acc += sz[grp * C + k] * __ldg(&W2[k * C + c]);
        s_red[tid] = fmaxf(acc, 0.0f) * __ldg(&fcW[tid]);
    }
    __syncthreads();
    for (int st = C; st > 0; st >>= 1) {
        if (tid < st) s_red[tid] += s_red[tid + st];
        __syncthreads();
    }
    if (tid == 0) out[0] = 1.0f / (1.0f + expf(-(s_red[0] + __ldg(&fcb[0]))));

    // ---- cleanup (parallel): restore zero-invariant for next replay ----
    __syncthreads();
    for (int i = tid; i < nf; i += 128) {
        int v = g_frontier[i];
        if ((unsigned)v < N_NODES) {
            g_frontbit[v >> 5] = 0u;
            g_bloom[bloom_bit(v) >> 5] = 0u;
        }
    }
    if (tid == 0) { g_cntA = 0; g_cntB = 0; g_nfront = 0; g_ne = 0; g_tick = 0; }
}

// ---------- launch ----------
extern "C" void kernel_launch(void* const* d_in, const int* in_sizes, int n_in,
                              void* d_out, int out_size) {
    const float* x    = (const float*)d_in[0];
    const void*  edge = d_in[1];
    const void*  pair = d_in[2];
    const float* W1   = (const float*)d_in[3];
    const float* b1   = (const float*)d_in[4];
    const float* W2   = (const float*)d_in[5];
    const float* b2   = (const float*)d_in[6];
    const float* fcW  = (const float*)d_in[7];
    const float* fcb  = (const float*)d_in[8];
    float* out = (float*)d_out;

    k_scan1<<<NB, TPB>>>(edge, pair);
    k_scan2<<<NB, TPB>>>(edge);
    k_layer1<<<K3B, 128>>>(edge, pair, x, W1, b1, W2, b2, fcW, fcb, out);
}